// round 1
// baseline (speedup 1.0000x reference)
#include <cuda_runtime.h>

// Problem constants (fixed shapes: B=64, C=3, H=W=256)
#define NCAT    5
#define NB      64              // batch
#define E_ELEM  196608          // C*H*W
#define E4      49152           // E_ELEM / 4  (float4 positions per sample)
#define THREADS 64
#define NBLOCKS (E4 / THREADS)  // 768
#define NPART   15              // per-block partials: 5 scaled, 5 abs, 5 un-total
#define EPSF    1e-6f

// -------- device scratch (static allocation only; no cudaMalloc allowed) ----
__device__ ulonglong2 g_un_sum[NCAT * E4];       // [5][E] floats as packed f32x2 pairs (~3.9MB)
__device__ int        g_order[NB];               // sample indices sorted by category
__device__ int        g_start[NCAT + 1];         // category segment starts into g_order
__device__ int        g_counts[NCAT];
__device__ float      g_part[NBLOCKS * NPART];   // per-block partial sums (pass 2)

// -------- packed f32x2 helpers (Blackwell) ---------------------------------
__device__ __forceinline__ unsigned long long f2_add(unsigned long long a, unsigned long long b) {
    unsigned long long r;
    asm("add.rn.f32x2 %0, %1, %2;" : "=l"(r) : "l"(a), "l"(b));
    return r;
}
__device__ __forceinline__ unsigned long long f2_fma(unsigned long long a, unsigned long long b,
                                                     unsigned long long c) {
    unsigned long long r;
    asm("fma.rn.f32x2 %0, %1, %2, %3;" : "=l"(r) : "l"(a), "l"(b), "l"(c));
    return r;
}
__device__ __forceinline__ void f2_unpack(unsigned long long v, float& lo, float& hi) {
    asm("mov.b64 {%0, %1}, %2;" : "=f"(lo), "=f"(hi) : "l"(v));
}

#define NEG1X2 0xBF800000BF800000ULL   // packed (-1.0f, -1.0f)
#define ABSM2  0x7FFFFFFF7FFFFFFFULL   // packed abs mask

// ---------------------------------------------------------------------------
// Kernel 0: build category counts / sorted sample order (trivial, 1 thread)
// ---------------------------------------------------------------------------
__global__ void k_setup(const int* __restrict__ de_id) {
    if (threadIdx.x != 0 || blockIdx.x != 0) return;
    int cnt[NCAT];
#pragma unroll
    for (int c = 0; c < NCAT; ++c) cnt[c] = 0;
    for (int b = 0; b < NB; ++b) {
        int c = de_id[b];
        c = c < 0 ? 0 : (c >= NCAT ? NCAT - 1 : c);
        cnt[c]++;
    }
    int st[NCAT + 1];
    st[0] = 0;
#pragma unroll
    for (int c = 0; c < NCAT; ++c) st[c + 1] = st[c] + cnt[c];
#pragma unroll
    for (int c = 0; c < NCAT; ++c) { g_counts[c] = cnt[c]; g_start[c] = st[c]; }
    g_start[NCAT] = st[NCAT];
    int pos[NCAT];
#pragma unroll
    for (int c = 0; c < NCAT; ++c) pos[c] = st[c];
    for (int b = 0; b < NB; ++b) {
        int c = de_id[b];
        c = c < 0 ? 0 : (c >= NCAT ? NCAT - 1 : c);
        g_order[pos[c]++] = b;
    }
}

// ---------------------------------------------------------------------------
// Kernel 1: un_sum[c][j] = sum over samples of category c of un[b][j]
// Thread owns one float4 position j, loops samples in sorted-by-cat order.
// ---------------------------------------------------------------------------
__global__ void k_pass1(const float* __restrict__ un) {
    __shared__ int s_off[NB];
    __shared__ int s_start[NCAT + 1];
    int tid = threadIdx.x;
    if (tid < NB)       s_off[tid]   = g_order[tid] * E4;
    if (tid < NCAT + 1) s_start[tid] = g_start[tid];
    __syncthreads();

    int j = blockIdx.x * THREADS + tid;
    const ulonglong2* __restrict__ up = reinterpret_cast<const ulonglong2*>(un);

#pragma unroll
    for (int c = 0; c < NCAT; ++c) {
        unsigned long long a0 = 0ull, a1 = 0ull;   // packed (0.f,0.f)
        int k  = s_start[c];
        int ke = s_start[c + 1];
        for (; k < ke; ++k) {
            ulonglong2 v = up[s_off[k] + j];
            a0 = f2_add(a0, v.x);
            a1 = f2_add(a1, v.y);
        }
        ulonglong2 o; o.x = a0; o.y = a1;
        g_un_sum[c * E4 + j] = o;
    }
}

// ---------------------------------------------------------------------------
// Kernel 2: per-category scaled-L1 / abs-L1 / un-totals.
// Accumulate |clean - restored| per position per category, multiply by the
// per-position scale s = 1/(un_sum/cnt + eps) only at category flush.
// ---------------------------------------------------------------------------
__global__ void k_pass2(const float* __restrict__ restored,
                        const float* __restrict__ clean) {
    __shared__ int   s_off[NB];
    __shared__ int   s_start[NCAT + 1];
    __shared__ float s_invc[NCAT];
    __shared__ float sred[NPART][THREADS];

    int tid = threadIdx.x;
    if (tid < NB)       s_off[tid]   = g_order[tid] * E4;
    if (tid < NCAT + 1) s_start[tid] = g_start[tid];
    if (tid < NCAT) {
        int c = g_counts[tid];
        s_invc[tid] = 1.0f / (float)(c > 0 ? c : 1);
    }
    __syncthreads();

    int j = blockIdx.x * THREADS + tid;
    const ulonglong2* __restrict__ rp = reinterpret_cast<const ulonglong2*>(restored);
    const ulonglong2* __restrict__ cp = reinterpret_cast<const ulonglong2*>(clean);

    float vals[NPART];

#pragma unroll
    for (int c = 0; c < NCAT; ++c) {
        unsigned long long A0 = 0ull, A1 = 0ull;   // packed abs-diff sums for this cat
        int k  = s_start[c];
        int ke = s_start[c + 1];
        for (; k < ke; ++k) {
            int off = s_off[k] + j;
            ulonglong2 r  = rp[off];
            ulonglong2 cl = cp[off];
            unsigned long long d0 = f2_fma(r.x, NEG1X2, cl.x);  // clean - restored
            unsigned long long d1 = f2_fma(r.y, NEG1X2, cl.y);
            d0 &= ABSM2;                                        // |.| both lanes
            d1 &= ABSM2;
            A0 = f2_add(A0, d0);
            A1 = f2_add(A1, d1);
        }
        // flush: load un_sum for this (cat, position), form s, dot with A
        ulonglong2 us = g_un_sum[c * E4 + j];
        float u0, u1, u2, u3;
        f2_unpack(us.x, u0, u1);
        f2_unpack(us.y, u2, u3);
        float ic = s_invc[c];
        float s0 = 1.0f / (u0 * ic + EPSF);
        float s1 = 1.0f / (u1 * ic + EPSF);
        float s2 = 1.0f / (u2 * ic + EPSF);
        float s3 = 1.0f / (u3 * ic + EPSF);
        float a0, a1, a2, a3;
        f2_unpack(A0, a0, a1);
        f2_unpack(A1, a2, a3);
        vals[c]      = fmaf(a3, s3, fmaf(a2, s2, fmaf(a1, s1, a0 * s0)));  // scaled sum
        vals[5 + c]  = (a0 + a1) + (a2 + a3);                               // abs sum
        vals[10 + c] = (u0 + u1) + (u2 + u3);                               // un total
    }

    // block reduction of 15 values
#pragma unroll
    for (int v = 0; v < NPART; ++v) sred[v][tid] = vals[v];
    __syncthreads();
#pragma unroll
    for (int st = THREADS / 2; st > 0; st >>= 1) {
        if (tid < st) {
#pragma unroll
            for (int v = 0; v < NPART; ++v) sred[v][tid] += sred[v][tid + st];
        }
        __syncthreads();
    }
    if (tid < NPART) g_part[blockIdx.x * NPART + tid] = sred[tid][0];
}

// ---------------------------------------------------------------------------
// Kernel 3: reduce per-block partials, compute the 21 outputs.
// ---------------------------------------------------------------------------
__global__ void k_finalize(float* __restrict__ out) {
    __shared__ float sseg[16][NPART];
    __shared__ float stot[NPART];
    int tid = threadIdx.x;

    if (tid < 16 * NPART) {                 // 240 threads: 16 segments x 15 columns
        int v = tid % NPART;
        int seg = tid / NPART;
        float s = 0.0f;
        const int rows = NBLOCKS / 16;      // 48
#pragma unroll 4
        for (int i = 0; i < rows; ++i)
            s += g_part[(seg * rows + i) * NPART + v];
        sseg[seg][v] = s;
    }
    __syncthreads();
    if (tid < NPART) {
        float s = 0.0f;
#pragma unroll
        for (int g = 0; g < 16; ++g) s += sseg[g][tid];
        stot[tid] = s;
    }
    __syncthreads();

    if (tid == 0) {
        const float Ef = (float)E_ELEM;
        float totalsum = 0.0f;
        float cum_sc = 0.0f;
        float cumN   = 0.0f;
        int   num_ne = 0;
#pragma unroll
        for (int c = 0; c < NCAT; ++c) if (g_counts[c] > 0) num_ne++;

#pragma unroll
        for (int c = 0; c < NCAT; ++c) {
            int   cnt  = g_counts[c];
            bool  ne   = cnt > 0;
            float safe = (float)(cnt > 0 ? cnt : 1);
            float S_sc = stot[c];
            float S_ab = stot[5 + c];
            float S_un = stot[10 + c];

            cum_sc += S_sc;
            cumN   += (float)cnt * Ef;
            float cum_l1  = cum_sc / fmaxf(cumN, 1.0f);
            float un_num  = S_un / (safe * Ef) + EPSF;
            float bn      = ne ? 2.0f * logf(un_num) : 0.0f;
            float unc     = ne ? cum_l1 : 0.0f;
            float old_l   = ne ? S_ab / (safe * Ef) : 0.0f;
            float cat_l   = unc + bn;
            totalsum += cat_l;

            out[1 + c]  = cat_l;
            out[6 + c]  = old_l;
            out[11 + c] = bn;
            out[16 + c] = unc;
        }
        out[0] = totalsum / (float)(num_ne > 0 ? num_ne : 1);
    }
}

// ---------------------------------------------------------------------------
extern "C" void kernel_launch(void* const* d_in, const int* in_sizes, int n_in,
                              void* d_out, int out_size) {
    const float* restored = (const float*)d_in[0];
    const float* clean    = (const float*)d_in[1];
    const int*   de_id    = (const int*)d_in[2];
    const float* un       = (const float*)d_in[3];
    float*       out      = (float*)d_out;

    k_setup<<<1, 32>>>(de_id);
    k_pass1<<<NBLOCKS, THREADS>>>(un);
    k_pass2<<<NBLOCKS, THREADS>>>(restored, clean);
    k_finalize<<<1, 256>>>(out);
}

// round 2
// speedup vs baseline: 1.4311x; 1.4311x over previous
#include <cuda_runtime.h>

// Fixed shapes: B=64, C=3, H=W=256
#define NCAT    5
#define NB      64
#define E_ELEM  196608
#define E4      49152           // float4 positions per sample
#define THREADS 64
#define NBLOCKS (E4 / THREADS)  // 768
#define NPART   15              // 5 scaled, 5 abs, 5 un-total
#define NPAD    16              // padded row for g_part (float4-aligned)
#define EPSF    1e-6f

__device__ float g_part[NBLOCKS * NPAD];
__device__ int   g_done = 0;    // self-resetting last-block counter

// -------- packed f32x2 helpers (Blackwell) ---------------------------------
__device__ __forceinline__ unsigned long long f2_add(unsigned long long a, unsigned long long b) {
    unsigned long long r;
    asm("add.rn.f32x2 %0, %1, %2;" : "=l"(r) : "l"(a), "l"(b));
    return r;
}
__device__ __forceinline__ unsigned long long f2_fma(unsigned long long a, unsigned long long b,
                                                     unsigned long long c) {
    unsigned long long r;
    asm("fma.rn.f32x2 %0, %1, %2, %3;" : "=l"(r) : "l"(a), "l"(b), "l"(c));
    return r;
}
__device__ __forceinline__ void f2_unpack(unsigned long long v, float& lo, float& hi) {
    asm("mov.b64 {%0, %1}, %2;" : "=f"(lo), "=f"(hi) : "l"(v));
}

#define NEG1X2 0xBF800000BF800000ULL   // packed (-1.0f, -1.0f)
#define ABSM2  0x7FFFFFFF7FFFFFFFULL   // packed abs mask

// ---------------------------------------------------------------------------
// Single fused kernel: setup + un_sum (registers) + scaled/abs L1 + finalize.
// ---------------------------------------------------------------------------
__global__ void __launch_bounds__(THREADS)
k_fused(const float* __restrict__ restored,
        const float* __restrict__ clean,
        const int*   __restrict__ de_id,
        const float* __restrict__ un,
        float*       __restrict__ out) {
    __shared__ int   s_id[NB];
    __shared__ int   s_off[NB];            // sorted-by-cat sample offsets (*E4)
    __shared__ int   s_start[NCAT + 1];
    __shared__ int   s_cnt[NCAT];
    __shared__ float s_invc[NCAT];
    __shared__ float sred[NPART][THREADS];
    __shared__ int   s_last;

    const int tid = threadIdx.x;

    // ---- per-block setup: categorize + sort samples (tiny, fully parallel blocks)
    s_id[tid] = de_id[tid];                // THREADS == NB == 64
    __syncthreads();
    if (tid == 0) {
        int cnt[NCAT];
#pragma unroll
        for (int c = 0; c < NCAT; ++c) cnt[c] = 0;
#pragma unroll
        for (int b = 0; b < NB; ++b) {
            int c = s_id[b];
            c = c < 0 ? 0 : (c >= NCAT ? NCAT - 1 : c);
            s_id[b] = c;
            cnt[c]++;
        }
        int st = 0;
#pragma unroll
        for (int c = 0; c < NCAT; ++c) {
            s_start[c] = st;
            s_cnt[c]   = cnt[c];
            s_invc[c]  = 1.0f / (float)(cnt[c] > 0 ? cnt[c] : 1);
            st += cnt[c];
        }
        s_start[NCAT] = st;
        int pos[NCAT];
#pragma unroll
        for (int c = 0; c < NCAT; ++c) pos[c] = s_start[c];
#pragma unroll
        for (int b = 0; b < NB; ++b) s_off[pos[s_id[b]]++] = b * E4;
    }
    __syncthreads();

    // ---- fused main loop: this thread owns float4 position j ----
    const int j = blockIdx.x * THREADS + tid;
    const ulonglong2* __restrict__ rp = reinterpret_cast<const ulonglong2*>(restored);
    const ulonglong2* __restrict__ cp = reinterpret_cast<const ulonglong2*>(clean);
    const ulonglong2* __restrict__ up = reinterpret_cast<const ulonglong2*>(un);

    float vals[NPART];

#pragma unroll
    for (int c = 0; c < NCAT; ++c) {
        unsigned long long U0 = 0ull, U1 = 0ull;   // un sums (packed)
        unsigned long long A0 = 0ull, A1 = 0ull;   // |clean-restored| sums (packed)
        int k  = s_start[c];
        int ke = s_start[c + 1];
#pragma unroll 4
        for (; k < ke; ++k) {
            int off = s_off[k] + j;
            ulonglong2 u  = up[off];
            ulonglong2 r  = rp[off];
            ulonglong2 cl = cp[off];
            U0 = f2_add(U0, u.x);
            U1 = f2_add(U1, u.y);
            unsigned long long d0 = f2_fma(r.x, NEG1X2, cl.x) & ABSM2;
            unsigned long long d1 = f2_fma(r.y, NEG1X2, cl.y) & ABSM2;
            A0 = f2_add(A0, d0);
            A1 = f2_add(A1, d1);
        }
        // flush: s = 1/(un_mean + eps), dot with abs-diff sums
        float u0, u1, u2, u3, a0, a1, a2, a3;
        f2_unpack(U0, u0, u1);
        f2_unpack(U1, u2, u3);
        f2_unpack(A0, a0, a1);
        f2_unpack(A1, a2, a3);
        float ic = s_invc[c];
        float s0 = 1.0f / (u0 * ic + EPSF);
        float s1 = 1.0f / (u1 * ic + EPSF);
        float s2 = 1.0f / (u2 * ic + EPSF);
        float s3 = 1.0f / (u3 * ic + EPSF);
        vals[c]      = fmaf(a3, s3, fmaf(a2, s2, fmaf(a1, s1, a0 * s0)));
        vals[5 + c]  = (a0 + a1) + (a2 + a3);
        vals[10 + c] = (u0 + u1) + (u2 + u3);
    }

    // ---- block reduction of 15 values ----
#pragma unroll
    for (int v = 0; v < NPART; ++v) sred[v][tid] = vals[v];
    __syncthreads();
#pragma unroll
    for (int st = THREADS / 2; st > 0; st >>= 1) {
        if (tid < st) {
#pragma unroll
            for (int v = 0; v < NPART; ++v) sred[v][tid] += sred[v][tid + st];
        }
        __syncthreads();
    }
    if (tid < NPART) g_part[blockIdx.x * NPAD + tid] = sred[tid][0];

    // ---- last-block finalize (deterministic: fixed-order reads) ----
    __syncthreads();
    __threadfence();
    if (tid == 0) s_last = (atomicAdd(&g_done, 1) == NBLOCKS - 1);
    __syncthreads();
    if (!s_last) return;

    __threadfence();
    {
        // 768 rows / 64 threads = 12 rows each; rows padded to 16 floats.
        float acc[NPART];
#pragma unroll
        for (int v = 0; v < NPART; ++v) acc[v] = 0.0f;
        const float4* gp4 = reinterpret_cast<const float4*>(g_part);
        int base = tid * 12 * (NPAD / 4);
#pragma unroll
        for (int r = 0; r < 12; ++r) {
            float4 q0 = __ldcg(gp4 + base + 0);
            float4 q1 = __ldcg(gp4 + base + 1);
            float4 q2 = __ldcg(gp4 + base + 2);
            float4 q3 = __ldcg(gp4 + base + 3);
            base += NPAD / 4;
            acc[0] += q0.x;  acc[1] += q0.y;  acc[2]  += q0.z;  acc[3]  += q0.w;
            acc[4] += q1.x;  acc[5] += q1.y;  acc[6]  += q1.z;  acc[7]  += q1.w;
            acc[8] += q2.x;  acc[9] += q2.y;  acc[10] += q2.z;  acc[11] += q2.w;
            acc[12] += q3.x; acc[13] += q3.y; acc[14] += q3.z;
        }
#pragma unroll
        for (int v = 0; v < NPART; ++v) sred[v][tid] = acc[v];
        __syncthreads();
#pragma unroll
        for (int st = THREADS / 2; st > 0; st >>= 1) {
            if (tid < st) {
#pragma unroll
                for (int v = 0; v < NPART; ++v) sred[v][tid] += sred[v][tid + st];
            }
            __syncthreads();
        }
        if (tid == 0) {
            const float Ef = (float)E_ELEM;
            float totalsum = 0.0f, cum_sc = 0.0f, cumN = 0.0f;
            int num_ne = 0;
#pragma unroll
            for (int c = 0; c < NCAT; ++c) if (s_cnt[c] > 0) num_ne++;
#pragma unroll
            for (int c = 0; c < NCAT; ++c) {
                int   cnt  = s_cnt[c];
                bool  ne   = cnt > 0;
                float safe = (float)(cnt > 0 ? cnt : 1);
                float S_sc = sred[c][0];
                float S_ab = sred[5 + c][0];
                float S_un = sred[10 + c][0];

                cum_sc += S_sc;
                cumN   += (float)cnt * Ef;
                float cum_l1 = cum_sc / fmaxf(cumN, 1.0f);
                float un_num = S_un / (safe * Ef) + EPSF;
                float bn     = ne ? 2.0f * logf(un_num) : 0.0f;
                float unc    = ne ? cum_l1 : 0.0f;
                float old_l  = ne ? S_ab / (safe * Ef) : 0.0f;
                float cat_l  = unc + bn;
                totalsum += cat_l;

                out[1 + c]  = cat_l;
                out[6 + c]  = old_l;
                out[11 + c] = bn;
                out[16 + c] = unc;
            }
            out[0] = totalsum / (float)(num_ne > 0 ? num_ne : 1);
            g_done = 0;   // self-reset for graph replay
        }
    }
}

// ---------------------------------------------------------------------------
extern "C" void kernel_launch(void* const* d_in, const int* in_sizes, int n_in,
                              void* d_out, int out_size) {
    const float* restored = (const float*)d_in[0];
    const float* clean    = (const float*)d_in[1];
    const int*   de_id    = (const int*)d_in[2];
    const float* un       = (const float*)d_in[3];
    float*       out      = (float*)d_out;

    k_fused<<<NBLOCKS, THREADS>>>(restored, clean, de_id, un, out);
}